// round 8
// baseline (speedup 1.0000x reference)
#include <cuda_runtime.h>
#include <math.h>

#define NHID 64
#define NMAX 400000
#define NXMAX 100000
#define NNZCAP 2200000
#define BN_EPS 1e-5f
#define NSM 148

typedef unsigned long long u64;

// ---------------- scratch (device globals; no allocations) ----------------
__device__ __align__(256) float  g_dn[NMAX];
__device__ __align__(256) float  g_de[NMAX];
__device__ __align__(256) float  g_h [NMAX * NHID];   // only rows >= Nold used
__device__ __align__(256) float  g_mn[NMAX * NHID];
__device__ __align__(256) float  g_me[NMAX * NHID];
__device__ __align__(256) float  g_t [NXMAX * NHID];
__device__ double g_sum[NHID];
__device__ double g_sumsq[NHID];
// CSR build scratch
__device__ __align__(256) int   g_cnt_n[NMAX], g_cnt_e[NMAX];
__device__ __align__(256) int   g_cur_n[NMAX], g_cur_e[NMAX];
__device__ __align__(256) int   g_start_n[NMAX], g_start_e[NMAX];
__device__ __align__(256) int2  g_pkn[NNZCAP], g_pke[NNZCAP];
__device__ int g_sflag[2][256];   // chained-scan publish flags (value = prefix+1)

// ---------------- packed f32x2 helpers ----------------
__device__ __forceinline__ u64 pack2(float lo, float hi) {
    u64 r; asm("mov.b64 %0, {%1,%2};" : "=l"(r) : "f"(lo), "f"(hi)); return r;
}
__device__ __forceinline__ float2 unpack2(u64 v) {
    float2 r; asm("mov.b64 {%0,%1}, %2;" : "=f"(r.x), "=f"(r.y) : "l"(v)); return r;
}
__device__ __forceinline__ void fma2(u64& acc, u64 a, u64 b) {
    asm("fma.rn.f32x2 %0, %1, %2, %0;" : "+l"(acc) : "l"(a), "l"(b));
}
__device__ __forceinline__ float sigmf(float x) {
    return __fdividef(1.0f, 1.0f + __expf(-x));
}
__device__ __forceinline__ float tanhfast(float x) {
    return 2.0f * sigmf(2.0f * x) - 1.0f;
}

// ---------------- K0: zero scratch (no h copy anymore) ----------------
__global__ void k_init(int N) {
    int i = blockIdx.x * blockDim.x + threadIdx.x;
    int stride = gridDim.x * blockDim.x;
    for (int j = i; j < N; j += stride) {
        g_dn[j] = 0.f; g_de[j] = 0.f;
        g_cnt_n[j] = 0; g_cnt_e[j] = 0;
        g_cur_n[j] = 0; g_cur_e[j] = 0;
    }
    if (i < 256) { g_sflag[0][i] = 0; g_sflag[1][i] = 0; }
    if (i < NHID) { g_sum[i] = 0.0; g_sumsq[i] = 0.0; }
}

// ---------------- K1: histogram + diagonal extraction ----------------
__global__ void k_hist(const int* __restrict__ nr, const int* __restrict__ nc,
                       const float* __restrict__ nv, int nnzN,
                       const int* __restrict__ er, const int* __restrict__ ec,
                       const float* __restrict__ ev, int nnzE) {
    int j = blockIdx.x * blockDim.x + threadIdx.x;
    int tot = nnzN + nnzE;
    if (j >= tot) return;
    if (j < nnzN) {
        int r = nr[j], c = nc[j];
        if (r == c) atomicAdd(&g_dn[r], nv[j]);
        else atomicAdd(&g_cnt_n[r], 1);
    } else {
        int e = j - nnzN;
        int r = er[e], c = ec[e];
        if (r == c) atomicAdd(&g_de[r], ev[e]);
        else atomicAdd(&g_cnt_e[r], 1);
    }
}

// ---------------- fused single-launch scan (chained block prefix) ------
// grid (nblk, 2); blockIdx.y: 0=node, 1=edge. Flags zeroed by k_init.
__global__ void k_scanf(int n) {
    int edge = blockIdx.y;
    const int* in = edge ? g_cnt_e : g_cnt_n;
    int* out = edge ? g_start_e : g_start_n;
    int* flag = g_sflag[edge];
    __shared__ int sh[256];
    __shared__ int sPrefix;
    int tid = threadIdx.x;
    int bid = blockIdx.x;
    int base = bid * 4096 + tid * 16;
    int loc[16]; int s = 0;
#pragma unroll
    for (int k = 0; k < 16; k++) {
        loc[k] = (base + k < n) ? in[base + k] : 0;
        s += loc[k];
    }
    sh[tid] = s; __syncthreads();
    for (int off = 1; off < 256; off <<= 1) {
        int t2 = (tid >= off) ? sh[tid - off] : 0;
        __syncthreads();
        sh[tid] += t2;
        __syncthreads();
    }
    int incl = sh[tid];          // block-local inclusive prefix for this thread
    int blockTotal = sh[255];
    // chain: wait for predecessor's global prefix
    if (tid == 0) {
        int prefix = 0;
        if (bid > 0) {
            int v;
            do { v = atomicAdd(&flag[bid - 1], 0); } while (v == 0);
            prefix = v - 1;
        }
        sPrefix = prefix;
        __threadfence();
        atomicExch(&flag[bid], prefix + blockTotal + 1);
    }
    __syncthreads();
    int prefix = sPrefix;
    int run = prefix + incl - s;
#pragma unroll
    for (int k = 0; k < 16; k++) {
        if (base + k < n) out[base + k] = run;
        run += loc[k];
    }
}

// ---------------- K-scatter: build packed CSR, filtered ----------------
__global__ void k_scatter(const int* __restrict__ nr, const int* __restrict__ nc,
                          const float* __restrict__ nv, int nnzN,
                          const int* __restrict__ er, const int* __restrict__ ec,
                          const float* __restrict__ ev, int nnzE) {
    int j = blockIdx.x * blockDim.x + threadIdx.x;
    int tot = nnzN + nnzE;
    if (j >= tot) return;
    if (j < nnzN) {
        int r = nr[j], c = nc[j];
        if (r != c && g_dn[r] != 0.f) {
            int p = g_start_n[r] + atomicAdd(&g_cur_n[r], 1);
            g_pkn[p] = make_int2(c, __float_as_int(nv[j]));
        }
    } else {
        int e = j - nnzN;
        int r = er[e], c = ec[e];
        if (r != c && g_de[r] != 0.f) {
            int p = g_start_e[r] + atomicAdd(&g_cur_e[r], 1);
            g_pke[p] = make_int2(c, __float_as_int(ev[e]));
        }
    }
}

// ---------------- K-spmm: warp/row, desc preload + shfl, indep gathers -
__global__ void k_spmm_csr(const float* __restrict__ h_in, int Nold, int N) {
    int w = (blockIdx.x * blockDim.x + threadIdx.x) >> 5;
    int lane = threadIdx.x & 31;
    if (w >= 2 * N) return;
    bool node = w < N;
    int r = node ? w : w - N;
    float scale = node ? g_dn[r] : g_de[r];
    if (scale == 0.f) return;   // row never consumed
    const int2* pk = node ? g_pkn : g_pke;
    int s = node ? g_start_n[r] : g_start_e[r];
    int cnt = node ? g_cur_n[r] : g_cur_e[r];
    int half = lane >> 4, l16 = lane & 15;
    // cooperative descriptor preload: one coalesced 8B/lane load
    int fast = cnt < 32 ? cnt : 32;
    int2 ec = (lane < fast) ? pk[s + lane] : make_int2(0, 0);
    float4 acc = make_float4(0.f, 0.f, 0.f, 0.f);
    for (int g = 0; g < fast; g += 2) {
        int idx = g + half;
        int cc = __shfl_sync(0xffffffffu, ec.x, idx);
        float vv = __int_as_float(__shfl_sync(0xffffffffu, ec.y, idx));
        if (idx < fast) {
            const float4* hp = (cc < Nold)
                ? reinterpret_cast<const float4*>(h_in + (size_t)cc * NHID)
                : reinterpret_cast<const float4*>(g_h + (size_t)cc * NHID);
            float4 hv = hp[l16];
            acc.x += vv * hv.x; acc.y += vv * hv.y;
            acc.z += vv * hv.z; acc.w += vv * hv.w;
        }
    }
    // generic tail (cnt > 32; essentially never taken on Poisson(4) rows)
    for (int p = s + 32; p < s + cnt; p++) {
        int2 e0 = pk[p];
        if (half == 0) {
            int cc = e0.x;
            const float4* hp = (cc < Nold)
                ? reinterpret_cast<const float4*>(h_in + (size_t)cc * NHID)
                : reinterpret_cast<const float4*>(g_h + (size_t)cc * NHID);
            float4 hv = hp[l16];
            float vv = __int_as_float(e0.y);
            acc.x += vv * hv.x; acc.y += vv * hv.y;
            acc.z += vv * hv.z; acc.w += vv * hv.w;
        }
    }
    acc.x += __shfl_xor_sync(0xffffffffu, acc.x, 16);
    acc.y += __shfl_xor_sync(0xffffffffu, acc.y, 16);
    acc.z += __shfl_xor_sync(0xffffffffu, acc.z, 16);
    acc.w += __shfl_xor_sync(0xffffffffu, acc.w, 16);
    if (half == 0) {
        float* M = node ? g_mn : g_me;
        reinterpret_cast<float4*>(M + (size_t)r * NHID)[l16] = acc;
    }
}

// ---------------- K3: lin1, thread-per-row ----------------
__global__ void __launch_bounds__(256) k_lin1(
    const float* __restrict__ x, const float* __restrict__ W1,
    const float* __restrict__ b1, int Nx) {
    __shared__ float sW[4096];
    __shared__ float sB[64];
    int tid = threadIdx.x;
    for (int t = tid; t < 4096; t += 256) sW[t] = W1[t];
    if (tid < 64) sB[tid] = b1[tid];
    __syncthreads();
    int i = blockIdx.x * 256 + tid;
    if (i >= Nx) return;
    u64 x2[32];
    const ulonglong2* xr = reinterpret_cast<const ulonglong2*>(x + (size_t)i * NHID);
#pragma unroll
    for (int k = 0; k < 16; k++) { ulonglong2 v = xr[k]; x2[2 * k] = v.x; x2[2 * k + 1] = v.y; }
    float4* o = reinterpret_cast<float4*>(g_t + (size_t)i * NHID);
    for (int jg = 0; jg < 16; jg++) {
        float res[4];
#pragma unroll
        for (int jj = 0; jj < 4; jj++) {
            int j = jg * 4 + jj;
            u64 acc = pack2(sB[j], 0.f);
            const ulonglong2* wr = reinterpret_cast<const ulonglong2*>(sW + j * 64);
#pragma unroll
            for (int k = 0; k < 16; k++) {
                ulonglong2 wv = wr[k];
                fma2(acc, x2[2 * k], wv.x);
                fma2(acc, x2[2 * k + 1], wv.y);
            }
            float2 p = unpack2(acc);
            res[jj] = p.x + p.y;
        }
        o[jg] = make_float4(res[0], res[1], res[2], res[3]);
    }
}

// ---------------- K-stats: BN batch stats from g_t ----------------
__global__ void k_stats(int Nx) {
    __shared__ float sS[64], sQ[64];
    int tid = threadIdx.x;
    if (tid < 64) { sS[tid] = 0.f; sQ[tid] = 0.f; }
    __syncthreads();
    int cc = tid & 15;
    float4 s = make_float4(0.f, 0.f, 0.f, 0.f);
    float4 q = make_float4(0.f, 0.f, 0.f, 0.f);
    for (int r = blockIdx.x * 16 + (tid >> 4); r < Nx; r += gridDim.x * 16) {
        float4 v = reinterpret_cast<const float4*>(g_t)[(size_t)r * 16 + cc];
        s.x += v.x; s.y += v.y; s.z += v.z; s.w += v.w;
        q.x += v.x * v.x; q.y += v.y * v.y; q.z += v.z * v.z; q.w += v.w * v.w;
    }
    int c0 = cc * 4;
    atomicAdd(&sS[c0], s.x); atomicAdd(&sS[c0 + 1], s.y);
    atomicAdd(&sS[c0 + 2], s.z); atomicAdd(&sS[c0 + 3], s.w);
    atomicAdd(&sQ[c0], q.x); atomicAdd(&sQ[c0 + 1], q.y);
    atomicAdd(&sQ[c0 + 2], q.z); atomicAdd(&sQ[c0 + 3], q.w);
    __syncthreads();
    if (tid < 64) {
        atomicAdd(&g_sum[tid], (double)sS[tid]);
        atomicAdd(&g_sumsq[tid], (double)sQ[tid]);
    }
}

// ---------------- K4: BN + ReLU + lin2 + h_update, thread-per-row ------
__global__ void __launch_bounds__(256) k_lin2(
    const float* __restrict__ gamma, const float* __restrict__ beta,
    const float* __restrict__ W2, const float* __restrict__ b2,
    int Nx, int Nold) {
    __shared__ float sW[4096];
    __shared__ float sB[64];
    __shared__ float sScale[64], sShift[64];
    int tid = threadIdx.x;
    for (int t = tid; t < 4096; t += 256) sW[t] = W2[t];
    if (tid < 64) {
        sB[tid] = b2[tid];
        double mu = g_sum[tid] / (double)Nx;
        double var = g_sumsq[tid] / (double)Nx - mu * mu;
        float inv = rsqrtf((float)var + BN_EPS);
        float sc = gamma[tid] * inv;
        sScale[tid] = sc;
        sShift[tid] = beta[tid] - (float)mu * sc;
    }
    __syncthreads();
    int i = blockIdx.x * 256 + tid;
    if (i >= Nx) return;
    u64 x2[32];
    const float4* tr = reinterpret_cast<const float4*>(g_t + (size_t)i * NHID);
#pragma unroll
    for (int k = 0; k < 16; k++) {
        float4 v = tr[k];
        int k0 = k * 4;
        v.x = fmaxf(v.x * sScale[k0] + sShift[k0], 0.f);
        v.y = fmaxf(v.y * sScale[k0 + 1] + sShift[k0 + 1], 0.f);
        v.z = fmaxf(v.z * sScale[k0 + 2] + sShift[k0 + 2], 0.f);
        v.w = fmaxf(v.w * sScale[k0 + 3] + sShift[k0 + 3], 0.f);
        x2[2 * k] = pack2(v.x, v.y);
        x2[2 * k + 1] = pack2(v.z, v.w);
    }
    float dn = g_dn[Nold + i];
    float4* o = reinterpret_cast<float4*>(g_h + (size_t)(Nold + i) * NHID);
    for (int jg = 0; jg < 16; jg++) {
        float res[4];
#pragma unroll
        for (int jj = 0; jj < 4; jj++) {
            int j = jg * 4 + jj;
            u64 acc = pack2(sB[j], 0.f);
            const ulonglong2* wr = reinterpret_cast<const ulonglong2*>(sW + j * 64);
#pragma unroll
            for (int k = 0; k < 16; k++) {
                ulonglong2 wv = wr[k];
                fma2(acc, x2[2 * k], wv.x);
                fma2(acc, x2[2 * k + 1], wv.y);
            }
            float2 p = unpack2(acc);
            res[jj] = (p.x + p.y) * dn;
        }
        o[jg] = make_float4(res[0], res[1], res[2], res[3]);
    }
}

// ---------------- K6: persistent dual-weight GRU + heads (j-unroll 2) --
#define SMG_BIAS 49152
#define SMG_WON  (SMG_BIAS + 768)
#define SMG_WOE  (SMG_WON + 64)
#define SMG_TOT  (SMG_WOE + 64)

__global__ void __launch_bounds__(256) k_gru(
    const float* __restrict__ h_in, int Nold,
    const float* __restrict__ Wi_n, const float* __restrict__ bi_n,
    const float* __restrict__ Wh_n, const float* __restrict__ bh_n,
    const float* __restrict__ Wi_e, const float* __restrict__ bi_e,
    const float* __restrict__ Wh_e, const float* __restrict__ bh_e,
    const float* __restrict__ w_on, const float* __restrict__ b_on,
    const float* __restrict__ w_oe, const float* __restrict__ b_oe,
    int N, float* __restrict__ out) {
    extern __shared__ float sm[];
    int tid = threadIdx.x;
    {
        float4* s4 = reinterpret_cast<float4*>(sm);
        const float4* a0 = reinterpret_cast<const float4*>(Wi_n);
        const float4* a1 = reinterpret_cast<const float4*>(Wh_n);
        const float4* a2 = reinterpret_cast<const float4*>(Wi_e);
        const float4* a3 = reinterpret_cast<const float4*>(Wh_e);
        for (int t = tid; t < 3072; t += 256) {
            s4[t] = a0[t];
            s4[3072 + t] = a1[t];
            s4[6144 + t] = a2[t];
            s4[9216 + t] = a3[t];
        }
        if (tid < 192) {
            sm[SMG_BIAS + tid] = bi_n[tid];
            sm[SMG_BIAS + 192 + tid] = bh_n[tid];
            sm[SMG_BIAS + 384 + tid] = bi_e[tid];
            sm[SMG_BIAS + 576 + tid] = bh_e[tid];
        }
        if (tid < 64) {
            sm[SMG_WON + tid] = w_on[tid];
            sm[SMG_WOE + tid] = w_oe[tid];
        }
    }
    __syncthreads();

    int wid = tid >> 5, lane = tid & 31;
    bool isNode = wid < 4;
    int local = isNode ? 2 * (wid * 32 + lane) : 2 * ((wid - 4) * 32 + lane) + 1;
    const float* mptr = isNode ? g_mn : g_me;
    const float* optr = isNode ? g_me : g_mn;
    const float* sWi = sm + (isNode ? 0 : 24576);
    const float* sWh = sWi + 12288;
    const float* sBi = sm + SMG_BIAS + (isNode ? 0 : 384);
    const float* sBh = sBi + 192;
    const float* gWi = isNode ? Wi_e : Wi_n;
    const float* gWh = isNode ? Wh_e : Wh_n;
    const float* gBi = isNode ? bi_e : bi_n;
    const float* gBh = isNode ? bh_e : bh_n;
    const float* sWon = sm + SMG_WON;
    const float* sWoe = sm + SMG_WOE;
    float* out_h = out + 2 * (size_t)N;
    float bon = b_on[0], boe = b_oe[0];

    u64 m2[32], h2[32];
    float hl[64];

    for (int base = blockIdx.x * 256; base < N; base += gridDim.x * 256) {
        int i = base + local;
        bool active = i < N;

        float dn_i = 0.f, de_i = 0.f;
        if (active) { dn_i = g_dn[i]; de_i = g_de[i]; }
        float scale  = isNode ? dn_i : de_i;
        float oscale = isNode ? de_i : dn_i;

        if (active) {
            const float4* h4 = (i < Nold)
                ? reinterpret_cast<const float4*>(h_in + (size_t)i * NHID)
                : reinterpret_cast<const float4*>(g_h + (size_t)i * NHID);
#pragma unroll
            for (int k = 0; k < 16; k++) {
                float4 a = h4[k];
                hl[4 * k] = a.x; hl[4 * k + 1] = a.y; hl[4 * k + 2] = a.z; hl[4 * k + 3] = a.w;
                h2[2 * k] = pack2(a.x, a.y);
                h2[2 * k + 1] = pack2(a.z, a.w);
            }
        }
        float s_on = 0.f, s_oe = 0.f;

        bool did_main = active && (scale != 0.f);
        if (did_main) {
            const ulonglong2* mm = reinterpret_cast<const ulonglong2*>(mptr + (size_t)i * NHID);
#pragma unroll
            for (int k = 0; k < 16; k++) {
                ulonglong2 mv = mm[k];
                m2[2 * k] = mv.x; m2[2 * k + 1] = mv.y;
            }
            for (int jp = 0; jp < 32; jp++) {
                int j0 = 2 * jp, j1 = 2 * jp + 1;
                u64 aR0 = pack2(sBi[j0], 0.f),     aR1 = pack2(sBi[j1], 0.f);
                u64 aZ0 = pack2(sBi[64 + j0], 0.f), aZ1 = pack2(sBi[64 + j1], 0.f);
                u64 aN0 = pack2(sBi[128 + j0], 0.f), aN1 = pack2(sBi[128 + j1], 0.f);
                u64 bR0 = pack2(sBh[j0], 0.f),     bR1 = pack2(sBh[j1], 0.f);
                u64 bZ0 = pack2(sBh[64 + j0], 0.f), bZ1 = pack2(sBh[64 + j1], 0.f);
                u64 bN0 = pack2(sBh[128 + j0], 0.f), bN1 = pack2(sBh[128 + j1], 0.f);
                const ulonglong2* w0 = reinterpret_cast<const ulonglong2*>(sWi + j0 * 64);
                const ulonglong2* w1 = reinterpret_cast<const ulonglong2*>(sWi + (64 + j0) * 64);
                const ulonglong2* w2 = reinterpret_cast<const ulonglong2*>(sWi + (128 + j0) * 64);
                const ulonglong2* v0 = reinterpret_cast<const ulonglong2*>(sWh + j0 * 64);
                const ulonglong2* v1 = reinterpret_cast<const ulonglong2*>(sWh + (64 + j0) * 64);
                const ulonglong2* v2 = reinterpret_cast<const ulonglong2*>(sWh + (128 + j0) * 64);
#pragma unroll
                for (int kk = 0; kk < 16; kk++) {
                    u64 ma = m2[2 * kk], mb = m2[2 * kk + 1];
                    u64 ha = h2[2 * kk], hb = h2[2 * kk + 1];
                    ulonglong2 W0a = w0[kk], W0b = w0[kk + 16];
                    ulonglong2 W1a = w1[kk], W1b = w1[kk + 16];
                    ulonglong2 W2a = w2[kk], W2b = w2[kk + 16];
                    ulonglong2 V0a = v0[kk], V0b = v0[kk + 16];
                    ulonglong2 V1a = v1[kk], V1b = v1[kk + 16];
                    ulonglong2 V2a = v2[kk], V2b = v2[kk + 16];
                    fma2(aR0, ma, W0a.x); fma2(aR0, mb, W0a.y);
                    fma2(aR1, ma, W0b.x); fma2(aR1, mb, W0b.y);
                    fma2(aZ0, ma, W1a.x); fma2(aZ0, mb, W1a.y);
                    fma2(aZ1, ma, W1b.x); fma2(aZ1, mb, W1b.y);
                    fma2(aN0, ma, W2a.x); fma2(aN0, mb, W2a.y);
                    fma2(aN1, ma, W2b.x); fma2(aN1, mb, W2b.y);
                    fma2(bR0, ha, V0a.x); fma2(bR0, hb, V0a.y);
                    fma2(bR1, ha, V0b.x); fma2(bR1, hb, V0b.y);
                    fma2(bZ0, ha, V1a.x); fma2(bZ0, hb, V1a.y);
                    fma2(bZ1, ha, V1b.x); fma2(bZ1, hb, V1b.y);
                    fma2(bN0, ha, V2a.x); fma2(bN0, hb, V2a.y);
                    fma2(bN1, ha, V2b.x); fma2(bN1, hb, V2b.y);
                }
                float2 t;
                t = unpack2(aR0); float pr0 = t.x + t.y;
                t = unpack2(aR1); float pr1 = t.x + t.y;
                t = unpack2(aZ0); float pz0 = t.x + t.y;
                t = unpack2(aZ1); float pz1 = t.x + t.y;
                t = unpack2(aN0); float pn0 = t.x + t.y;
                t = unpack2(aN1); float pn1 = t.x + t.y;
                t = unpack2(bR0); float qr0 = t.x + t.y;
                t = unpack2(bR1); float qr1 = t.x + t.y;
                t = unpack2(bZ0); float qz0 = t.x + t.y;
                t = unpack2(bZ1); float qz1 = t.x + t.y;
                t = unpack2(bN0); float qn0 = t.x + t.y;
                t = unpack2(bN1); float qn1 = t.x + t.y;
                float r0 = sigmf(pr0 + qr0), r1 = sigmf(pr1 + qr1);
                float z0 = sigmf(pz0 + qz0), z1 = sigmf(pz1 + qz1);
                float ng0 = tanhfast(pn0 + r0 * qn0), ng1 = tanhfast(pn1 + r1 * qn1);
                float hf0 = scale * ((1.f - z0) * ng0 + z0 * hl[j0]);
                float hf1 = scale * ((1.f - z1) * ng1 + z1 * hl[j1]);
                reinterpret_cast<float2*>(out_h + (size_t)i * NHID)[jp] = make_float2(hf0, hf1);
                s_on += hf0 * sWon[j0] + hf1 * sWon[j1];
                s_oe += hf0 * sWoe[j0] + hf1 * sWoe[j1];
            }
        } else if (active) {
            float4 z4 = make_float4(0.f, 0.f, 0.f, 0.f);
            float4* o4 = reinterpret_cast<float4*>(out_h + (size_t)i * NHID);
#pragma unroll
            for (int k = 0; k < 16; k++) o4[k] = z4;
        }

        // rare general fallback (both dn,de nonzero) — weights from global
        bool need2 = active && (oscale != 0.f);
        if (need2) {
            s_on = 0.f; s_oe = 0.f;
            const float* mo = optr + (size_t)i * NHID;
            float ml[64];
#pragma unroll
            for (int k = 0; k < 64; k++) ml[k] = mo[k];
            for (int j = 0; j < NHID; j++) {
                float ir = gBi[j], iz = gBi[64 + j], in_ = gBi[128 + j];
                float hr = gBh[j], hz = gBh[64 + j], hn = gBh[128 + j];
                for (int k = 0; k < 64; k++) {
                    ir += ml[k] * gWi[j * 64 + k];
                    iz += ml[k] * gWi[(64 + j) * 64 + k];
                    in_ += ml[k] * gWi[(128 + j) * 64 + k];
                    hr += hl[k] * gWh[j * 64 + k];
                    hz += hl[k] * gWh[(64 + j) * 64 + k];
                    hn += hl[k] * gWh[(128 + j) * 64 + k];
                }
                float r = sigmf(ir + hr);
                float z = sigmf(iz + hz);
                float ng = tanhfast(in_ + r * hn);
                float hv = (1.f - z) * ng + z * hl[j];
                size_t oi = (size_t)i * NHID + j;
                float hf = out_h[oi] + oscale * hv;
                out_h[oi] = hf;
                s_on += hf * sWon[j];
                s_oe += hf * sWoe[j];
            }
        }

        if (active) {
            float y = dn_i * (s_on + bon) + de_i * (s_oe + boe);
            out[i] = sigmf(y);
            out[(size_t)N + i] = y;
        }
    }
}

// ---------------- launch ----------------
extern "C" void kernel_launch(void* const* d_in, const int* in_sizes, int n_in,
                              void* d_out, int out_size) {
    const float* x     = (const float*)d_in[0];
    const float* h_in  = (const float*)d_in[1];
    const int*   nr    = (const int*)d_in[2];
    const int*   nc    = (const int*)d_in[3];
    const float* nv    = (const float*)d_in[4];
    const int*   er    = (const int*)d_in[5];
    const int*   ec    = (const int*)d_in[6];
    const float* ev    = (const float*)d_in[7];
    const float* W1    = (const float*)d_in[8];
    const float* b1    = (const float*)d_in[9];
    const float* gamma = (const float*)d_in[10];
    const float* beta  = (const float*)d_in[11];
    const float* W2    = (const float*)d_in[12];
    const float* b2    = (const float*)d_in[13];
    const float* Wi_n  = (const float*)d_in[14];
    const float* bi_n  = (const float*)d_in[15];
    const float* Wh_n  = (const float*)d_in[16];
    const float* bh_n  = (const float*)d_in[17];
    const float* Wi_e  = (const float*)d_in[18];
    const float* bi_e  = (const float*)d_in[19];
    const float* Wh_e  = (const float*)d_in[20];
    const float* bh_e  = (const float*)d_in[21];
    const float* w_on  = (const float*)d_in[22];
    const float* b_on  = (const float*)d_in[23];
    const float* w_oe  = (const float*)d_in[24];
    const float* b_oe  = (const float*)d_in[25];

    int Nx   = in_sizes[0] / NHID;
    int Nold = in_sizes[1] / NHID;
    int N    = Nx + Nold;
    int nnzN = in_sizes[2];
    int nnzE = in_sizes[5];
    float* out = (float*)d_out;

    cudaFuncSetAttribute(k_gru, cudaFuncAttributeMaxDynamicSharedMemorySize,
                         SMG_TOT * sizeof(float));

    int tot = nnzN + nnzE;
    int nblk = (N + 4095) / 4096;

    k_init<<<512, 256>>>(N);                                          // 1
    k_hist<<<(tot + 255) / 256, 256>>>(nr, nc, nv, nnzN, er, ec, ev, nnzE); // 2
    {
        dim3 g1(nblk, 2);
        k_scanf<<<g1, 256>>>(N);                                      // 3
    }
    k_scatter<<<(tot + 255) / 256, 256>>>(nr, nc, nv, nnzN, er, ec, ev, nnzE); // 4 (profiled)

    k_lin1<<<(Nx + 255) / 256, 256>>>(x, W1, b1, Nx);                 // 5
    k_stats<<<256, 256>>>(Nx);                                        // 6
    k_lin2<<<(Nx + 255) / 256, 256>>>(gamma, beta, W2, b2, Nx, Nold); // 7

    {
        long long warps = 2LL * N;
        int blocks = (int)((warps * 32 + 255) / 256);
        k_spmm_csr<<<blocks, 256>>>(h_in, Nold, N);                   // 8
    }

    k_gru<<<NSM, 256, SMG_TOT * sizeof(float)>>>(                     // 9
        h_in, Nold,
        Wi_n, bi_n, Wh_n, bh_n, Wi_e, bi_e, Wh_e, bh_e,
        w_on, b_on, w_oe, b_oe, N, out);
}